// round 3
// baseline (speedup 1.0000x reference)
#include <cuda_runtime.h>
#include <cstdint>

#define Hh 512
#define Ww 512
#define Cc 32
#define Bb 4
#define Ss (Hh*Ww)

// Scratch: per-pixel (off_x, off_y), 4*512*512*8B = 8 MB
__device__ float2 g_off_buf[Bb * Ss];

typedef unsigned long long ull;

__device__ __forceinline__ ull pack2(float a, float b) {
    ull r;
    asm("mov.b64 %0, {%1, %2};" : "=l"(r) : "f"(a), "f"(b));
    return r;
}
__device__ __forceinline__ void unpack2(ull v, float& a, float& b) {
    asm("mov.b64 {%0, %1}, %2;" : "=f"(a), "=f"(b) : "l"(v));
}
__device__ __forceinline__ ull fma2(ull a, ull b, ull c) {
    ull d;
    asm("fma.rn.f32x2 %0, %1, %2, %3;" : "=l"(d) : "l"(a), "l"(b), "l"(c));
    return d;
}

// ---------------------------------------------------------------------------
// Kernel 1: offset conv (only channels 0,1 of the 18 are consumed downstream).
// 32x32 tile, 128 threads, thread = 4 cols x 2 rows, channel loop with
// double-buffered smem staging. R3 fix: the 6-value row window is loaded as
// LDS.128 + LDS.64 (16B-aligned: row pitch 36 floats = 144B, col offset 16cg)
// instead of 24 scalar LDS that were 4-way bank-conflicted (the ~100us loss).
// ---------------------------------------------------------------------------
__global__ __launch_bounds__(128) void conv_off_kernel(
    const float* __restrict__ x,
    const float* __restrict__ w_off,
    const float* __restrict__ b_off)
{
    const int tid = threadIdx.x;
    const int cg = tid & 7;    // col group: cols 4cg..4cg+3
    const int rg = tid >> 3;   // row group: rows 2rg, 2rg+1
    const int bx = blockIdx.x, by = blockIdx.y, bz = blockIdx.z;

    __shared__ float2 s_w[Cc * 9];        // packed (w0, w1) per (c, k)
    __shared__ float  s_tile[2][34 * 36]; // (32+2) rows x (32+2 cols pad 36)

    for (int i = tid; i < Cc * 9; i += 128)
        s_w[i] = make_float2(w_off[i], w_off[288 + i]);

    const int gx0 = bx * 32 - 1;
    const int gy0 = by * 32 - 1;
    const float* xb = x + (size_t)bz * Cc * Ss;

    auto stage = [&](int c, float* buf) {
        const float* xc = xb + (size_t)c * Ss;
        for (int i = tid; i < 34 * 34; i += 128) {
            int r = i / 34;
            int q = i - r * 34;
            int gy = gy0 + r;
            int gx = gx0 + q;
            float v = 0.0f;
            if ((unsigned)gy < (unsigned)Hh && (unsigned)gx < (unsigned)Ww)
                v = __ldg(xc + gy * Ww + gx);
            buf[r * 36 + q] = v;
        }
    };

    stage(0, s_tile[0]);
    const float b0v = __ldg(b_off + 0);
    const float b1v = __ldg(b_off + 1);
    __syncthreads();

    ull acc[8];
    const ull biasp = pack2(b0v, b1v);
#pragma unroll
    for (int i = 0; i < 8; i++) acc[i] = biasp;

    for (int c = 0; c < Cc; c++) {
        const float* curp = s_tile[c & 1];

        ull wk[9];
#pragma unroll
        for (int k = 0; k < 9; k++) {
            float2 t = s_w[c * 9 + k];
            wk[k] = pack2(t.x, t.y);
        }

        // Vectorized window load: 4 rows x (LDS.128 + LDS.64), both aligned.
        ull pv[4][6];
#pragma unroll
        for (int r = 0; r < 4; r++) {
            const float* rowp = curp + (2 * rg + r) * 36 + 4 * cg;
            float4 q4 = *reinterpret_cast<const float4*>(rowp);
            float2 q2 = *reinterpret_cast<const float2*>(rowp + 4);
            pv[r][0] = pack2(q4.x, q4.x);
            pv[r][1] = pack2(q4.y, q4.y);
            pv[r][2] = pack2(q4.z, q4.z);
            pv[r][3] = pack2(q4.w, q4.w);
            pv[r][4] = pack2(q2.x, q2.x);
            pv[r][5] = pack2(q2.y, q2.y);
        }

        if (c + 1 < Cc) stage(c + 1, s_tile[(c + 1) & 1]);

#pragma unroll
        for (int pr = 0; pr < 2; pr++) {
#pragma unroll
            for (int pc = 0; pc < 4; pc++) {
                ull a = acc[pr * 4 + pc];
#pragma unroll
                for (int ky = 0; ky < 3; ky++) {
#pragma unroll
                    for (int kx = 0; kx < 3; kx++) {
                        a = fma2(pv[pr + ky][pc + kx], wk[ky * 3 + kx], a);
                    }
                }
                acc[pr * 4 + pc] = a;
            }
        }
        __syncthreads();
    }

    // write offsets (single-use scratch: streaming stores, keep L2 for x)
#pragma unroll
    for (int pr = 0; pr < 2; pr++) {
#pragma unroll
        for (int pc = 0; pc < 4; pc++) {
            int y = by * 32 + 2 * rg + pr;
            int xcol = bx * 32 + 4 * cg + pc;
            float ox, oy;
            unpack2(acc[pr * 4 + pc], ox, oy);
            __stcs(&g_off_buf[bz * Ss + y * Ww + xcol], make_float2(ox, oy));
        }
    }
}

// ---------------------------------------------------------------------------
// Kernel 2: bilinear sampling with zero padding. One thread per pixel, 32
// channels looped with corner indices/weights hoisted. Corner clamping and
// validity handled independently from the raw integer coords (jnp semantics).
// ---------------------------------------------------------------------------
__global__ __launch_bounds__(256) void sample_kernel(
    const float* __restrict__ x,
    float* __restrict__ out)
{
    const int px = blockIdx.x * 64 + threadIdx.x;
    const int py = blockIdx.y * 4 + threadIdx.y;
    const int b  = blockIdx.z;

    float2 off = __ldcs(&g_off_buf[b * Ss + py * Ww + px]);
    float ix = (float)px + off.x;
    float iy = (float)py + off.y;

    float x0f = floorf(ix);
    float y0f = floorf(iy);
    float wx1 = ix - x0f, wx0 = 1.0f - wx1;
    float wy1 = iy - y0f, wy0 = 1.0f - wy1;

    float fx0 = (x0f >= 0.0f && x0f <= 511.0f) ? 1.0f : 0.0f;
    float fx1 = (x0f >= -1.0f && x0f <= 510.0f) ? 1.0f : 0.0f;
    float fy0 = (y0f >= 0.0f && y0f <= 511.0f) ? 1.0f : 0.0f;
    float fy1 = (y0f >= -1.0f && y0f <= 510.0f) ? 1.0f : 0.0f;

    int ix0r = (int)x0f;
    int iy0r = (int)y0f;
    int xi0 = max(0, min(511, ix0r));
    int xi1 = max(0, min(511, ix0r + 1));
    int yi0 = max(0, min(511, iy0r));
    int yi1 = max(0, min(511, iy0r + 1));

    float w00 = wy0 * wx0 * (fy0 * fx0);
    float w01 = wy0 * wx1 * (fy0 * fx1);
    float w10 = wy1 * wx0 * (fy1 * fx0);
    float w11 = wy1 * wx1 * (fy1 * fx1);

    const int i00 = yi0 * Ww + xi0;
    const int i01 = yi0 * Ww + xi1;
    const int i10 = yi1 * Ww + xi0;
    const int i11 = yi1 * Ww + xi1;

    const float* xb = x + (size_t)b * Cc * Ss;
    size_t o = (size_t)b * Cc * Ss + (size_t)py * Ww + px;

#pragma unroll 4
    for (int c = 0; c < Cc; c++) {
        const float* p = xb + (size_t)c * Ss;
        float v = w00 * __ldg(p + i00)
                + w01 * __ldg(p + i01)
                + w10 * __ldg(p + i10)
                + w11 * __ldg(p + i11);
        __stcs(out + o + (size_t)c * Ss, v);
    }
}

extern "C" void kernel_launch(void* const* d_in, const int* in_sizes, int n_in,
                              void* d_out, int out_size)
{
    const float* x     = (const float*)d_in[0];  // (4, 32, 512, 512)
    const float* w_off = (const float*)d_in[1];  // (18, 32, 3, 3)
    const float* b_off = (const float*)d_in[2];  // (18,)
    float* out = (float*)d_out;                  // (4, 32, 512, 512)

    (void)in_sizes; (void)n_in; (void)out_size;

    dim3 g1(Ww / 32, Hh / 32, Bb);
    conv_off_kernel<<<g1, 128>>>(x, w_off, b_off);

    dim3 g2(Ww / 64, Hh / 4, Bb);
    dim3 t2(64, 4);
    sample_kernel<<<g2, t2>>>(x, out);
}

// round 4
// speedup vs baseline: 1.2611x; 1.2611x over previous
#include <cuda_runtime.h>
#include <cstdint>

#define Hh 512
#define Ww 512
#define Cc 32
#define Bb 4
#define Ss (Hh*Ww)

// Scratch: per-pixel (off_x, off_y), 4*512*512*8B = 8 MB
__device__ float2 g_off_buf[Bb * Ss];

typedef unsigned long long ull;

__device__ __forceinline__ ull pack2(float a, float b) {
    ull r;
    asm("mov.b64 %0, {%1, %2};" : "=l"(r) : "f"(a), "f"(b));
    return r;
}
__device__ __forceinline__ void unpack2(ull v, float& a, float& b) {
    asm("mov.b64 {%0, %1}, %2;" : "=f"(a), "=f"(b) : "l"(v));
}
__device__ __forceinline__ ull fma2(ull a, ull b, ull c) {
    ull d;
    asm("fma.rn.f32x2 %0, %1, %2, %3;" : "=l"(d) : "l"(a), "l"(b), "l"(c));
    return d;
}

// ---------------------------------------------------------------------------
// Kernel 1: offset conv (only channels 0,1 of the 18 are consumed downstream).
//
// R4 redesign: the old version staged ONE channel per __syncthreads (32 serial
// latency-bound phases ~600cyc each => ~134us). Now stage EIGHT channels per
// phase (39KB smem), so each block has only 4 stage->compute phases and each
// stage issues ~37 independent LDGs per thread (bandwidth-bound, not
// latency-bound).
//
// Block: 256 threads over a 32x32 pixel tile; thread = 2x2 pixels.
// Accumulate (off_x, off_y) packed as f32x2.
// ---------------------------------------------------------------------------
#define CG 8              // channels per staging group
#define TPITCH 36         // padded smem row pitch (floats)

__global__ __launch_bounds__(256) void conv_off_kernel(
    const float* __restrict__ x,
    const float* __restrict__ w_off,
    const float* __restrict__ b_off)
{
    const int tid = threadIdx.x;
    const int tx = tid & 15;    // 2*tx .. 2*tx+1 cols
    const int ty = tid >> 4;    // 2*ty .. 2*ty+1 rows
    const int bx = blockIdx.x, by = blockIdx.y, bz = blockIdx.z;

    __shared__ float2 s_w[Cc * 9];              // packed (w_ch0, w_ch1)
    __shared__ float  s_tile[CG][34 * TPITCH];  // 8 channels, 34x34 (+pad)

    for (int i = tid; i < Cc * 9; i += 256)
        s_w[i] = make_float2(w_off[i], w_off[288 + i]);

    const int gx0 = bx * 32 - 1;
    const int gy0 = by * 32 - 1;
    const float* xb = x + (size_t)bz * Cc * Ss;

    const float b0v = __ldg(b_off + 0);
    const float b1v = __ldg(b_off + 1);

    ull acc[4];
    const ull biasp = pack2(b0v, b1v);
#pragma unroll
    for (int i = 0; i < 4; i++) acc[i] = biasp;

    for (int g = 0; g < Cc / CG; g++) {
        // ---- stage 8 channels (high-MLP, bandwidth-bound) ----
#pragma unroll
        for (int c8 = 0; c8 < CG; c8++) {
            const float* xc = xb + (size_t)(g * CG + c8) * Ss;
            float* buf = s_tile[c8];
#pragma unroll
            for (int i = tid; i < 34 * 34; i += 256) {
                int r = i / 34;
                int q = i - r * 34;
                int gy = gy0 + r;
                int gx = gx0 + q;
                float v = 0.0f;
                if ((unsigned)gy < (unsigned)Hh && (unsigned)gx < (unsigned)Ww)
                    v = __ldg(xc + gy * Ww + gx);
                buf[r * TPITCH + q] = v;
            }
        }
        __syncthreads();

        // ---- compute 8 channels from smem ----
#pragma unroll
        for (int c8 = 0; c8 < CG; c8++) {
            const float* curp = s_tile[c8];

            ull wk[9];
#pragma unroll
            for (int k = 0; k < 9; k++) {
                float2 t = s_w[(g * CG + c8) * 9 + k];
                wk[k] = pack2(t.x, t.y);
            }

            // 4x4 input window at (2ty, 2tx): 4 rows x 2 aligned LDS.64
            ull pv[4][4];
#pragma unroll
            for (int r = 0; r < 4; r++) {
                const float2* rp = reinterpret_cast<const float2*>(
                    curp + (2 * ty + r) * TPITCH + 2 * tx);
                float2 a = rp[0];
                float2 bq = rp[1];
                pv[r][0] = pack2(a.x, a.x);
                pv[r][1] = pack2(a.y, a.y);
                pv[r][2] = pack2(bq.x, bq.x);
                pv[r][3] = pack2(bq.y, bq.y);
            }

            // 2x2 output pixels, 9 taps each
#pragma unroll
            for (int pr = 0; pr < 2; pr++) {
#pragma unroll
                for (int pc = 0; pc < 2; pc++) {
                    ull a = acc[pr * 2 + pc];
#pragma unroll
                    for (int ky = 0; ky < 3; ky++) {
#pragma unroll
                        for (int kx = 0; kx < 3; kx++) {
                            a = fma2(pv[pr + ky][pc + kx], wk[ky * 3 + kx], a);
                        }
                    }
                    acc[pr * 2 + pc] = a;
                }
            }
        }
        __syncthreads();
    }

    // write offsets (single-use scratch: streaming stores, keep L2 for x)
#pragma unroll
    for (int pr = 0; pr < 2; pr++) {
#pragma unroll
        for (int pc = 0; pc < 2; pc++) {
            int y = by * 32 + 2 * ty + pr;
            int xcol = bx * 32 + 2 * tx + pc;
            float ox, oy;
            unpack2(acc[pr * 2 + pc], ox, oy);
            __stcs(&g_off_buf[bz * Ss + y * Ww + xcol], make_float2(ox, oy));
        }
    }
}

// ---------------------------------------------------------------------------
// Kernel 2: bilinear sampling with zero padding. One thread per pixel, 32
// channels looped with corner indices/weights hoisted. Corner clamping and
// validity handled independently from the raw integer coords (jnp semantics).
// ---------------------------------------------------------------------------
__global__ __launch_bounds__(256) void sample_kernel(
    const float* __restrict__ x,
    float* __restrict__ out)
{
    const int px = blockIdx.x * 64 + threadIdx.x;
    const int py = blockIdx.y * 4 + threadIdx.y;
    const int b  = blockIdx.z;

    float2 off = __ldcs(&g_off_buf[b * Ss + py * Ww + px]);
    float ix = (float)px + off.x;
    float iy = (float)py + off.y;

    float x0f = floorf(ix);
    float y0f = floorf(iy);
    float wx1 = ix - x0f, wx0 = 1.0f - wx1;
    float wy1 = iy - y0f, wy0 = 1.0f - wy1;

    float fx0 = (x0f >= 0.0f && x0f <= 511.0f) ? 1.0f : 0.0f;
    float fx1 = (x0f >= -1.0f && x0f <= 510.0f) ? 1.0f : 0.0f;
    float fy0 = (y0f >= 0.0f && y0f <= 511.0f) ? 1.0f : 0.0f;
    float fy1 = (y0f >= -1.0f && y0f <= 510.0f) ? 1.0f : 0.0f;

    int ix0r = (int)x0f;
    int iy0r = (int)y0f;
    int xi0 = max(0, min(511, ix0r));
    int xi1 = max(0, min(511, ix0r + 1));
    int yi0 = max(0, min(511, iy0r));
    int yi1 = max(0, min(511, iy0r + 1));

    float w00 = wy0 * wx0 * (fy0 * fx0);
    float w01 = wy0 * wx1 * (fy0 * fx1);
    float w10 = wy1 * wx0 * (fy1 * fx0);
    float w11 = wy1 * wx1 * (fy1 * fx1);

    const int i00 = yi0 * Ww + xi0;
    const int i01 = yi0 * Ww + xi1;
    const int i10 = yi1 * Ww + xi0;
    const int i11 = yi1 * Ww + xi1;

    const float* xb = x + (size_t)b * Cc * Ss;
    size_t o = (size_t)b * Cc * Ss + (size_t)py * Ww + px;

#pragma unroll 4
    for (int c = 0; c < Cc; c++) {
        const float* p = xb + (size_t)c * Ss;
        float v = w00 * __ldg(p + i00)
                + w01 * __ldg(p + i01)
                + w10 * __ldg(p + i10)
                + w11 * __ldg(p + i11);
        __stcs(out + o + (size_t)c * Ss, v);
    }
}

extern "C" void kernel_launch(void* const* d_in, const int* in_sizes, int n_in,
                              void* d_out, int out_size)
{
    const float* x     = (const float*)d_in[0];  // (4, 32, 512, 512)
    const float* w_off = (const float*)d_in[1];  // (18, 32, 3, 3)
    const float* b_off = (const float*)d_in[2];  // (18,)
    float* out = (float*)d_out;                  // (4, 32, 512, 512)

    (void)in_sizes; (void)n_in; (void)out_size;

    dim3 g1(Ww / 32, Hh / 32, Bb);
    conv_off_kernel<<<g1, 256>>>(x, w_off, b_off);

    dim3 g2(Ww / 64, Hh / 4, Bb);
    dim3 t2(64, 4);
    sample_kernel<<<g2, t2>>>(x, out);
}